// round 14
// baseline (speedup 1.0000x reference)
#include <cuda_runtime.h>

#define BATCH 64
#define CH 3
#define IMG 640
#define PH 20
#define POOL 32
#define KDIM 1200
#define NQ 300
#define NCCOLS 84
#define NTOT 25200          // NQ * NCCOLS
#define NHALF 12600         // NTOT / 2 (two cols per thread)
#define TOPK 150
#define BT 8                // batch tile per GEMM block (8 b-sweeps => 792 blocks/panel)
#define PAIRS (BT / 2)      // 4 f32x2-packed batch pairs per block
#define NPAIRS (BATCH / 2)  // 32 total pairs
#define KCMAX 248           // Eigen threaded kc (FROZEN: matches reference bits)
#define NPANEL 5            // 248,248,248,248,208

__device__ unsigned long long g_pp[KDIM * NPAIRS];   // packed pairs [k][pair]
__device__ float g_part[NPANEL][BATCH * NTOT];       // per-panel partials, 32 MB
__device__ float g_scores[BATCH * NQ];
__device__ int   g_ids[BATCH * NQ];

typedef unsigned long long ull;

__device__ __forceinline__ ull pack2(float lo, float hi) {
    ull r; asm("mov.b64 %0, {%1, %2};" : "=l"(r) : "f"(lo), "f"(hi)); return r;
}
__device__ __forceinline__ ull dup2(float w) {
    ull r; asm("mov.b64 %0, {%1, %1};" : "=l"(r) : "f"(w)); return r;
}
__device__ __forceinline__ void fma2(ull& acc, ull a, ull b) {
    asm("fma.rn.f32x2 %0, %1, %2, %0;" : "+l"(acc) : "l"(a), "l"(b));
}
__device__ __forceinline__ void unpack2(ull v, float& lo, float& hi) {
    asm("mov.b64 {%0, %1}, %2;" : "=f"(lo), "=f"(hi) : "l"(v));
}

// ---------------------------------------------------------------------------
// Fused role kernel, grid (99, 8, 2):
//  z==1: POOL role — slice [kbase, kbase+klen): 32x32 mean pool + BGR flip.
//        pooled = fl( exact_int_sum * fl(1/261120) )  (FROZEN NUMERICS);
//        int sum < 2^24 exact. One warp per cell, ~5 cells/warp, writes the
//        packed GEMM layout ((float*)g_pp)[k*64 + b].
//  z==0: GEMM role — Eigen kc=248 panel `pan` (skip if pan<0): ascending-k
//        fused-FMA chain per (batch, n) from 0 into g_part[pan] (FROZEN).
//        2-column register blocking (n, n+12600), BT=8.
// Dependencies across launches are stream-ordered: launch i runs GEMM panel
// i-1 alongside pool slice i.
// ---------------------------------------------------------------------------
__global__ void __launch_bounds__(128) fused_kernel(
        const float* __restrict__ W, const int* __restrict__ x,
        int pan, int kbase, int klen) {

    if (blockIdx.z == 1) {
        // ---------------- POOL role ----------------
        if (klen <= 0) return;
        int nwarps = gridDim.x * gridDim.y * 4;                  // 3168
        int wid = (blockIdx.y * gridDim.x + blockIdx.x) * 4 + (threadIdx.x >> 5);
        int lane = threadIdx.x & 31;
        int ncells = BATCH * klen;
        int rowoff = lane >> 3;            // 0..3
        int coloff = (lane & 7) * 4;       // 0,4,..,28 (ints)
        for (int cell = wid; cell < ncells; cell += nwarps) {
            int b  = cell / klen;
            int kk = kbase + cell % klen;
            int c   = kk / 400;            // kk = c*400 + ph*20 + pw
            int rem = kk % 400;
            int ph = rem / 20;
            int pw = rem % 20;
            int c_in = 2 - c;              // BGR flip
            const int* base = x + (((long)(b * CH + c_in) * IMG + ph * POOL) * IMG)
                                + pw * POOL;
            int sum = 0;
#pragma unroll
            for (int r = 0; r < POOL; r += 4) {
                int4 v = *(const int4*)(base + (r + rowoff) * IMG + coloff);
                sum += v.x + v.y + v.z + v.w;
            }
#pragma unroll
            for (int s = 16; s; s >>= 1) sum += __shfl_xor_sync(0xffffffffu, sum, s);
            if (lane == 0)
                ((float*)g_pp)[kk * BATCH + b] = (float)sum * (1.0f / 261120.0f);
        }
        return;
    }

    // ---------------- GEMM role ----------------
    if (pan < 0) return;
    __shared__ ull p_s[KCMAX][PAIRS];        // 7.9 KB
    int k0  = pan * KCMAX;
    int len = (pan == NPANEL - 1) ? (KDIM - 4 * KCMAX) : KCMAX;   // 208 last
    int n0 = blockIdx.x * 128 + threadIdx.x; // col 0: [0, 12600)
    int pbase = blockIdx.y * PAIRS;          // this block's 4 pairs
    bool active = (n0 < NHALF);
    int n1 = n0 + NHALF;                     // col 1: [12600, 25200)

    // coalesced tile fill (g_pp is L2-resident)
    for (int idx = threadIdx.x; idx < len * PAIRS; idx += 128) {
        int kk = idx >> 2, pp = idx & 3;
        p_s[kk][pp] = g_pp[(k0 + kk) * NPAIRS + pbase + pp];
    }
    __syncthreads();

    ull acc0[PAIRS], acc1[PAIRS];
#pragma unroll
    for (int i = 0; i < PAIRS; i++) { acc0[i] = 0ull; acc1[i] = 0ull; }

    if (active) {
        const float* wpa = W + (long)k0 * NTOT + n0;
        const float* wpb = W + (long)k0 * NTOT + n1;
        for (int kk = 0; kk < len; kk += 4) {
            float a0 = wpa[0];
            float a1 = wpa[NTOT];
            float a2 = wpa[2 * NTOT];
            float a3 = wpa[3 * NTOT];
            float c0 = wpb[0];
            float c1 = wpb[NTOT];
            float c2 = wpb[2 * NTOT];
            float c3 = wpb[3 * NTOT];
            wpa += 4 * (long)NTOT;
            wpb += 4 * (long)NTOT;
            ull A0 = dup2(a0), A1 = dup2(a1), A2 = dup2(a2), A3 = dup2(a3);
            ull C0 = dup2(c0), C1 = dup2(c1), C2 = dup2(c2), C3 = dup2(c3);
#pragma unroll
            for (int h = 0; h < PAIRS / 2; h++) {
                ulonglong2 q0 = *(const ulonglong2*)&p_s[kk + 0][2 * h];
                ulonglong2 q1 = *(const ulonglong2*)&p_s[kk + 1][2 * h];
                ulonglong2 q2 = *(const ulonglong2*)&p_s[kk + 2][2 * h];
                ulonglong2 q3 = *(const ulonglong2*)&p_s[kk + 3][2 * h];
                // strictly ascending k per accumulator chain (FROZEN)
                fma2(acc0[2 * h], q0.x, A0);
                fma2(acc0[2 * h], q1.x, A1);
                fma2(acc0[2 * h], q2.x, A2);
                fma2(acc0[2 * h], q3.x, A3);
                fma2(acc0[2 * h + 1], q0.y, A0);
                fma2(acc0[2 * h + 1], q1.y, A1);
                fma2(acc0[2 * h + 1], q2.y, A2);
                fma2(acc0[2 * h + 1], q3.y, A3);
                fma2(acc1[2 * h], q0.x, C0);
                fma2(acc1[2 * h], q1.x, C1);
                fma2(acc1[2 * h], q2.x, C2);
                fma2(acc1[2 * h], q3.x, C3);
                fma2(acc1[2 * h + 1], q0.y, C0);
                fma2(acc1[2 * h + 1], q1.y, C1);
                fma2(acc1[2 * h + 1], q2.y, C2);
                fma2(acc1[2 * h + 1], q3.y, C3);
            }
        }

        float* part = g_part[pan];
#pragma unroll
        for (int pp = 0; pp < PAIRS; pp++) {
            long rA = (long)(2 * (pbase + pp))     * NTOT;
            long rB = (long)(2 * (pbase + pp) + 1) * NTOT;
            float ya, yb;
            unpack2(acc0[pp], ya, yb);
            part[rA + n0] = ya; part[rB + n0] = yb;
            unpack2(acc1[pp], ya, yb);
            part[rA + n1] = ya; part[rB + n1] = yb;
        }
    }
}

// ---------------------------------------------------------------------------
// Kernel 3: score + argmax with fused FROZEN panel merge:
// y[col] = ((((p0+p1)+p2)+p3)+p4), then max/argmax over 80 class cols
// (ties -> lower index, matches jnp.argmax). One warp per (b,q).
// ---------------------------------------------------------------------------
__global__ void score_kernel() {
    int warp = (blockIdx.x * blockDim.x + threadIdx.x) >> 5;
    int lane = threadIdx.x & 31;
    if (warp >= BATCH * NQ) return;
    long rowoff = (long)warp * NCCOLS;   // warp = b*NQ + q
    float best = -3.4e38f;
    int bidx = 0x7fffffff;
    for (int j = lane; j < 80; j += 32) {
        long e = rowoff + 4 + j;
        float v = g_part[0][e];          // FROZEN merge order
        v = v + g_part[1][e];
        v = v + g_part[2][e];
        v = v + g_part[3][e];
        v = v + g_part[4][e];
        if (v > best) { best = v; bidx = j; }
    }
#pragma unroll
    for (int s = 16; s; s >>= 1) {
        float ov = __shfl_xor_sync(0xffffffffu, best, s);
        int   oi = __shfl_xor_sync(0xffffffffu, bidx, s);
        if (ov > best || (ov == best && oi < bidx)) { best = ov; bidx = oi; }
    }
    if (lane == 0) { g_scores[warp] = best; g_ids[warp] = bidx; }
}

// ---------------------------------------------------------------------------
// Kernel 4: per-batch stable top-150 by rank counting (descending, ties by
// lower index — matches lax.top_k). Boxes merged from partials in FROZEN
// order. One block per batch.
// ---------------------------------------------------------------------------
__global__ void __launch_bounds__(320) topk_kernel(float* __restrict__ out) {
    __shared__ float s[NQ];
    int b = blockIdx.x;
    for (int q = threadIdx.x; q < NQ; q += 320) s[q] = g_scores[b * NQ + q];
    __syncthreads();
    int q = threadIdx.x;
    if (q < NQ) {
        float v = s[q];
        int rank = 0;
        for (int j = 0; j < NQ; j++) {
            float u = s[j];
            rank += (u > v) || (u == v && j < q);
        }
        if (rank < TOPK) {
            float* o = out + (long)(b * TOPK + rank) * 6;
            long rowoff = ((long)b * NQ + q) * NCCOLS;
#pragma unroll
            for (int c = 0; c < 4; c++) {
                float bx = g_part[0][rowoff + c];    // FROZEN merge order
                bx = bx + g_part[1][rowoff + c];
                bx = bx + g_part[2][rowoff + c];
                bx = bx + g_part[3][rowoff + c];
                bx = bx + g_part[4][rowoff + c];
                o[c] = bx;
            }
            o[4] = v;
            o[5] = (float)g_ids[b * NQ + q];
        }
    }
}

extern "C" void kernel_launch(void* const* d_in, const int* in_sizes, int n_in,
                              void* d_out, int out_size) {
    const int*   x = (const int*)d_in[0];
    const float* W = (const float*)d_in[1];
    float* out = (float*)d_out;

    dim3 g(99, BATCH / BT, 2);   // (99, 8, 2): z=0 GEMM role, z=1 pool role

    // L0: pool slice 0 only
    fused_kernel<<<g, 128>>>(W, x, -1, 0, KCMAX);
    // L1..L5: gemm panel p  ||  pool slice p+1 (stream order = dependency)
    for (int p = 0; p < NPANEL; p++) {
        int nb = (p + 1) * KCMAX;
        int nl = (p + 1 < NPANEL)
                   ? ((p + 1 == NPANEL - 1) ? (KDIM - 4 * KCMAX) : KCMAX)
                   : 0;
        fused_kernel<<<g, 128>>>(W, x, p, nb, nl);
    }

    score_kernel<<<(BATCH * NQ * 32 + 255) / 256, 256>>>();
    topk_kernel<<<BATCH, 320>>>(out);
}